// round 1
// baseline (speedup 1.0000x reference)
#include <cuda_runtime.h>
#include <math.h>

#define BB 2
#define NQ 256
#define NK 2048
#define DIM 256
#define NH 8
#define HD 32
#define NPTS 8
#define NCELL 1000

#define ATT_THREADS 512
#define KPT (NK / ATT_THREADS)   // 4

// scratch (device globals — no allocation allowed)
__device__ float g_tables[NPTS * NCELL * NH];   // [i][cell=z*100+y*10+x][h]
__device__ float g_qproj[BB * NQ * DIM];        // [b*NQ+q][h*32+d]
__device__ float g_kproj[BB * NK * HD];
__device__ float g_vproj[BB * NK * HD];
__device__ float g_xmid [BB * NQ * DIM];

// -------------------- CPB tables --------------------
__global__ void k_tables(const float* __restrict__ w1, const float* __restrict__ b1,
                         const float* __restrict__ w2) {
    int gid = blockIdx.x * blockDim.x + threadIdx.x;
    if (gid >= NPTS * NCELL) return;
    int i = gid / NCELL;
    int cell = gid % NCELL;
    int p = cell / 100, q = (cell / 10) % 10, r = cell % 10;
    const float step = 8.0f / 9.0f;
    float lp = -4.0f + p * step, lq = -4.0f + q * step, lr = -4.0f + r * step;
    const float* w1i = w1 + i * 3 * 128;
    const float* b1i = b1 + i * 128;
    const float* w2i = w2 + i * 128 * 8;
    float acc[8] = {0,0,0,0,0,0,0,0};
    for (int d = 0; d < 128; d++) {
        float h = lp * w1i[d] + lq * w1i[128 + d] + lr * w1i[256 + d] + b1i[d];
        h = fmaxf(h, 0.0f);
        const float* w2d = w2i + d * 8;
        #pragma unroll
        for (int hh = 0; hh < 8; hh++) acc[hh] += h * w2d[hh];
    }
    float* out = g_tables + gid * 8;
    #pragma unroll
    for (int hh = 0; hh < 8; hh++) out[hh] = acc[hh];
}

// -------------------- Q projection --------------------
__global__ void k_qproj(const float* __restrict__ query, const float* __restrict__ w,
                        const float* __restrict__ bias) {
    __shared__ float row[DIM];
    int rid = blockIdx.x;               // b*NQ + nq
    int b = rid >> 8, nq = rid & 255;
    int t = threadIdx.x;
    row[t] = query[(nq * BB + b) * DIM + t];   // query is (nQ, B, DIM)
    __syncthreads();
    float acc = bias[t];
    #pragma unroll 4
    for (int c = 0; c < DIM; c++) acc += row[c] * w[c * DIM + t];
    g_qproj[rid * DIM + t] = acc;
}

// -------------------- K/V projection --------------------
__global__ void k_kvproj(const float* __restrict__ key,
                         const float* __restrict__ kw, const float* __restrict__ kb,
                         const float* __restrict__ vw, const float* __restrict__ vb) {
    __shared__ float row[DIM];
    int rid = blockIdx.x;               // b*NK + kk
    int b = rid >> 11, kk = rid & 2047;
    int t = threadIdx.x;                // 64 threads
    for (int c = t; c < DIM; c += 64) row[c] = key[(kk * BB + b) * DIM + c];
    __syncthreads();
    int j = t & 31;
    const float* w  = (t < 32) ? kw : vw;
    float acc       = (t < 32) ? kb[j] : vb[j];
    #pragma unroll 4
    for (int c = 0; c < DIM; c++) acc += row[c] * w[c * HD + j];
    if (t < 32) g_kproj[rid * HD + j] = acc;
    else        g_vproj[rid * HD + j] = acc;
}

// -------------------- attention megakernel --------------------
__device__ __forceinline__ float xform(float dd) {
    float g = log2f(fabsf(dd) * 512.0f + 1.0f) * (1.0f / 12.0f);
    return copysignf(g, dd);
}

__global__ void __launch_bounds__(ATT_THREADS, 1)
k_attn(const float* __restrict__ refpt, const float* __restrict__ xyz,
       float* __restrict__ out_attn) {
    extern __shared__ float sm[];
    float* s_scores = sm;                         // NH*NK = 16384
    float* s_tbl    = sm + NH * NK;               // 2*NCELL*NH = 16000
    float* s_q      = s_tbl + 2 * NCELL * NH;     // 256
    float* s_rp     = s_q + DIM;                  // 24
    float* s_red    = s_rp + 24;                  // 400

    int t = threadIdx.x;
    int bq = blockIdx.x;
    int b = bq >> 8, nq = bq & 255;

    if (t < DIM) s_q[t]  = g_qproj[bq * DIM + t];
    if (t < 24)  s_rp[t] = refpt[bq * 24 + t];    // refpt (B,nQ,8,3) contiguous per (b,q)
    __syncthreads();

    // ---- QK^T ----
    float kx[KPT], ky[KPT], kz[KPT];
    const float scale = 0.17677669529663687f;     // 1/sqrt(32)
    #pragma unroll
    for (int m = 0; m < KPT; m++) {
        int k = t + m * ATT_THREADS;
        const float* kv = g_kproj + (b * NK + k) * HD;
        float kvv[HD];
        #pragma unroll
        for (int d = 0; d < HD; d += 4) {
            float4 f = *(const float4*)(kv + d);
            kvv[d] = f.x; kvv[d+1] = f.y; kvv[d+2] = f.z; kvv[d+3] = f.w;
        }
        const float* xv = xyz + (b * NK + k) * 3;
        kx[m] = xv[0]; ky[m] = xv[1]; kz[m] = xv[2];
        #pragma unroll
        for (int h = 0; h < NH; h++) {
            float acc = 0.f;
            #pragma unroll
            for (int d = 0; d < HD; d++) acc += s_q[h * HD + d] * kvv[d];
            s_scores[h * NK + k] = acc * scale;
        }
    }

    // ---- RPE: 4 passes, 2 tables in smem each ----
    for (int pass = 0; pass < 4; pass++) {
        __syncthreads();
        const float4* src = (const float4*)(g_tables + pass * 2 * NCELL * NH);
        float4* dst = (float4*)s_tbl;
        for (int idx = t; idx < 2 * NCELL * NH / 4; idx += ATT_THREADS) dst[idx] = src[idx];
        __syncthreads();
        #pragma unroll
        for (int m = 0; m < KPT; m++) {
            int k = t + m * ATT_THREADS;
            float acc[NH] = {0,0,0,0,0,0,0,0};
            #pragma unroll
            for (int ii = 0; ii < 2; ii++) {
                int i = pass * 2 + ii;
                float gx = xform(s_rp[i*3+0] - kx[m]);
                float gy = xform(s_rp[i*3+1] - ky[m]);
                float gz = xform(s_rp[i*3+2] - kz[m]);
                float fx = (gx + 1.f) * 4.5f, fy = (gy + 1.f) * 4.5f, fz = (gz + 1.f) * 4.5f;
                float x0f = floorf(fx), y0f = floorf(fy), z0f = floorf(fz);
                float wx1 = fx - x0f, wy1 = fy - y0f, wz1 = fz - z0f;
                int x0 = (int)x0f, y0 = (int)y0f, z0 = (int)z0f;
                const float* base = s_tbl + ii * NCELL * NH;
                #pragma unroll
                for (int c = 0; c < 8; c++) {
                    int dz = c >> 2, dy = (c >> 1) & 1, dx = c & 1;
                    int iz = z0 + dz, iy = y0 + dy, ix = x0 + dx;
                    if ((unsigned)iz < 10u && (unsigned)iy < 10u && (unsigned)ix < 10u) {
                        float w = (dz ? wz1 : 1.f - wz1) * (dy ? wy1 : 1.f - wy1) * (dx ? wx1 : 1.f - wx1);
                        const float* tb = base + (iz * 100 + iy * 10 + ix) * NH;
                        float4 a  = *(const float4*)tb;
                        float4 a2 = *(const float4*)(tb + 4);
                        acc[0] += w * a.x;  acc[1] += w * a.y;  acc[2] += w * a.z;  acc[3] += w * a.w;
                        acc[4] += w * a2.x; acc[5] += w * a2.y; acc[6] += w * a2.z; acc[7] += w * a2.w;
                    }
                }
            }
            #pragma unroll
            for (int h = 0; h < NH; h++) s_scores[h * NK + k] += acc[h];
        }
    }
    __syncthreads();

    // ---- softmax (per head over NK) ----
    int lane = t & 31, wid = t >> 5;  // 16 warps
    #pragma unroll
    for (int h = 0; h < NH; h++) {
        float v = -1e30f;
        #pragma unroll
        for (int m = 0; m < KPT; m++) v = fmaxf(v, s_scores[h * NK + t + m * ATT_THREADS]);
        #pragma unroll
        for (int o = 16; o; o >>= 1) v = fmaxf(v, __shfl_xor_sync(0xffffffffu, v, o));
        if (lane == 0) s_red[h * 16 + wid] = v;
    }
    __syncthreads();
    if (t < NH) {
        float v = s_red[t * 16];
        for (int w2 = 1; w2 < 16; w2++) v = fmaxf(v, s_red[t * 16 + w2]);
        s_red[128 + t] = v;
    }
    __syncthreads();
    #pragma unroll
    for (int h = 0; h < NH; h++) {
        float mh = s_red[128 + h];
        float v = 0.f;
        #pragma unroll
        for (int m = 0; m < KPT; m++) {
            int k = t + m * ATT_THREADS;
            float e = expf(s_scores[h * NK + k] - mh);
            s_scores[h * NK + k] = e;
            v += e;
        }
        #pragma unroll
        for (int o = 16; o; o >>= 1) v += __shfl_xor_sync(0xffffffffu, v, o);
        if (lane == 0) s_red[h * 16 + wid] = v;
    }
    __syncthreads();
    if (t < NH) {
        float v = 0.f;
        for (int w2 = 0; w2 < 16; w2++) v += s_red[t * 16 + w2];
        s_red[136 + t] = 1.0f / v;
    }
    __syncthreads();
    #pragma unroll
    for (int h = 0; h < NH; h++) {
        float r = s_red[136 + h];
        #pragma unroll
        for (int m = 0; m < KPT; m++) {
            int k = t + m * ATT_THREADS;
            float p = s_scores[h * NK + k] * r;
            s_scores[h * NK + k] = p;
            out_attn[((size_t)(b * NH + h) * NQ + nq) * NK + k] = p;
        }
    }
    __syncthreads();

    // ---- AV: 512 threads = 2 k-halves x (8 heads x 32 dims) ----
    int half = t >> 8;
    int idx  = t & 255;
    int h = idx >> 5, d = idx & 31;
    float acc = 0.f;
    const float* vbase = g_vproj + b * NK * HD;
    int k0 = half * (NK / 2);
    int k1 = k0 + (NK / 2);
    for (; k0 < k1; k0 += 4) {
        float4 p = *(const float4*)&s_scores[h * NK + k0];
        acc += p.x * vbase[(k0 + 0) * HD + d];
        acc += p.y * vbase[(k0 + 1) * HD + d];
        acc += p.z * vbase[(k0 + 2) * HD + d];
        acc += p.w * vbase[(k0 + 3) * HD + d];
    }
    if (half) s_red[144 + idx] = acc;
    __syncthreads();
    if (!half) g_xmid[bq * DIM + idx] = acc + s_red[144 + idx];
}

// -------------------- output projection (+ transpose to (nQ,B,DIM)) --------------------
__global__ void k_proj(const float* __restrict__ w, const float* __restrict__ bias,
                       float* __restrict__ out_x) {
    __shared__ float row[DIM];
    int rid = blockIdx.x;               // b*NQ + nq
    int b = rid >> 8, nq = rid & 255;
    int t = threadIdx.x;
    row[t] = g_xmid[rid * DIM + t];
    __syncthreads();
    float acc = bias[t];
    #pragma unroll 4
    for (int c = 0; c < DIM; c++) acc += row[c] * w[c * DIM + t];
    out_x[(nq * BB + b) * DIM + t] = acc;
}

// -------------------- launch --------------------
extern "C" void kernel_launch(void* const* d_in, const int* in_sizes, int n_in,
                              void* d_out, int out_size) {
    const float* query = (const float*)d_in[0];
    const float* key   = (const float*)d_in[1];
    const float* refpt = (const float*)d_in[2];
    // d_in[3] reference_angle: unused by the reference computation
    const float* xyz   = (const float*)d_in[4];
    const float* q_w   = (const float*)d_in[5];
    const float* q_b   = (const float*)d_in[6];
    const float* k_w   = (const float*)d_in[7];
    const float* k_b   = (const float*)d_in[8];
    const float* v_w   = (const float*)d_in[9];
    const float* v_b   = (const float*)d_in[10];
    const float* p_w   = (const float*)d_in[11];
    const float* p_b   = (const float*)d_in[12];
    const float* w1    = (const float*)d_in[13];
    const float* b1    = (const float*)d_in[14];
    const float* w2    = (const float*)d_in[15];

    float* out_x    = (float*)d_out;                       // (nQ, B, DIM)
    float* out_attn = (float*)d_out + BB * NQ * DIM;       // (B, NH, nQ, nK)

    const int smem_bytes = (NH * NK + 2 * NCELL * NH + DIM + 24 + 400) * (int)sizeof(float);
    cudaFuncSetAttribute(k_attn, cudaFuncAttributeMaxDynamicSharedMemorySize, smem_bytes);

    k_tables<<<(NPTS * NCELL + 255) / 256, 256>>>(w1, b1, w2);
    k_qproj <<<BB * NQ, 256>>>(query, q_w, q_b);
    k_kvproj<<<BB * NK, 64>>>(key, k_w, k_b, v_w, v_b);
    k_attn  <<<BB * NQ, ATT_THREADS, smem_bytes>>>(refpt, xyz, out_attn);
    k_proj  <<<BB * NQ, 256>>>(p_w, p_b, out_x);
}

// round 2
// speedup vs baseline: 1.2278x; 1.2278x over previous
#include <cuda_runtime.h>
#include <cuda_fp16.h>
#include <math.h>

#define BB 2
#define NQ 256
#define NK 2048
#define DIM 256
#define NH 8
#define HD 32
#define NPTS 8
#define NCELL 1000

#define ATT_THREADS 512
#define KPT (NK / ATT_THREADS)   // 4

// scratch (device globals — no allocation allowed)
__device__ __half g_tables[NPTS * NCELL * NH];  // [i][cell=z*100+y*10+x][h], fp16
__device__ float g_qproj[BB * NQ * DIM];        // [b*NQ+q][h*32+d]
__device__ float g_kproj[BB * NK * HD];
__device__ float g_vproj[BB * NK * HD];
__device__ float g_xmid [BB * NQ * DIM];

// -------------------- CPB tables --------------------
__global__ void k_tables(const float* __restrict__ w1, const float* __restrict__ b1,
                         const float* __restrict__ w2) {
    int gid = blockIdx.x * blockDim.x + threadIdx.x;
    if (gid >= NPTS * NCELL) return;
    int i = gid / NCELL;
    int cell = gid % NCELL;
    int p = cell / 100, q = (cell / 10) % 10, r = cell % 10;
    const float step = 8.0f / 9.0f;
    float lp = -4.0f + p * step, lq = -4.0f + q * step, lr = -4.0f + r * step;
    const float* w1i = w1 + i * 3 * 128;
    const float* b1i = b1 + i * 128;
    const float* w2i = w2 + i * 128 * 8;
    float acc[8] = {0,0,0,0,0,0,0,0};
    for (int d = 0; d < 128; d++) {
        float h = lp * w1i[d] + lq * w1i[128 + d] + lr * w1i[256 + d] + b1i[d];
        h = fmaxf(h, 0.0f);
        const float* w2d = w2i + d * 8;
        #pragma unroll
        for (int hh = 0; hh < 8; hh++) acc[hh] += h * w2d[hh];
    }
    __half* out = g_tables + gid * 8;
    #pragma unroll
    for (int hh = 0; hh < 8; hh++) out[hh] = __float2half(acc[hh]);
}

// -------------------- Q projection --------------------
__global__ void k_qproj(const float* __restrict__ query, const float* __restrict__ w,
                        const float* __restrict__ bias) {
    __shared__ float row[DIM];
    int rid = blockIdx.x;               // b*NQ + nq
    int b = rid >> 8, nq = rid & 255;
    int t = threadIdx.x;
    row[t] = query[(nq * BB + b) * DIM + t];   // query is (nQ, B, DIM)
    __syncthreads();
    float acc = bias[t];
    #pragma unroll 4
    for (int c = 0; c < DIM; c++) acc += row[c] * w[c * DIM + t];
    g_qproj[rid * DIM + t] = acc;
}

// -------------------- K/V projection --------------------
__global__ void k_kvproj(const float* __restrict__ key,
                         const float* __restrict__ kw, const float* __restrict__ kb,
                         const float* __restrict__ vw, const float* __restrict__ vb) {
    __shared__ float row[DIM];
    int rid = blockIdx.x;               // b*NK + kk
    int b = rid >> 11, kk = rid & 2047;
    int t = threadIdx.x;                // 64 threads
    for (int c = t; c < DIM; c += 64) row[c] = key[(kk * BB + b) * DIM + c];
    __syncthreads();
    int j = t & 31;
    const float* w  = (t < 32) ? kw : vw;
    float acc       = (t < 32) ? kb[j] : vb[j];
    #pragma unroll 4
    for (int c = 0; c < DIM; c++) acc += row[c] * w[c * HD + j];
    if (t < 32) g_kproj[rid * HD + j] = acc;
    else        g_vproj[rid * HD + j] = acc;
}

// -------------------- attention megakernel --------------------
__device__ __forceinline__ float xform(float dd) {
    float g = log2f(fabsf(dd) * 512.0f + 1.0f) * (1.0f / 12.0f);
    return copysignf(g, dd);
}

// smem layout (floats unless noted):
//   s_tbl  : __half[NPTS*NCELL*NH] = 64000 halves = 128000 B (16B-aligned at base)
//   s_scores: float[NH*NK]         = 65536 B
//   s_q    : float[DIM]
//   s_rp   : float[24]
//   s_red  : float[400]
#define SM_TBL_HALVES (NPTS * NCELL * NH)          // 64000
#define SM_SCORES_OFF (SM_TBL_HALVES / 2)          // in floats: 32000
#define SM_Q_OFF      (SM_SCORES_OFF + NH * NK)
#define SM_RP_OFF     (SM_Q_OFF + DIM)
#define SM_RED_OFF    (SM_RP_OFF + 24)
#define SM_TOTAL_F    (SM_RED_OFF + 400)

__global__ void __launch_bounds__(ATT_THREADS, 1)
k_attn(const float* __restrict__ refpt, const float* __restrict__ xyz,
       float* __restrict__ out_attn) {
    extern __shared__ float sm[];
    __half* s_tbl   = (__half*)sm;
    float* s_scores = sm + SM_SCORES_OFF;
    float* s_q      = sm + SM_Q_OFF;
    float* s_rp     = sm + SM_RP_OFF;
    float* s_red    = sm + SM_RED_OFF;

    int t = threadIdx.x;
    int bq = blockIdx.x;
    int b = bq >> 8, nq = bq & 255;

    if (t < DIM) s_q[t]  = g_qproj[bq * DIM + t];
    if (t < 24)  s_rp[t] = refpt[bq * 24 + t];    // refpt (B,nQ,8,3) contiguous per (b,q)

    // stage all 8 tables (fp16, 128000 B) into smem
    {
        const uint4* src = (const uint4*)g_tables;
        uint4* dst = (uint4*)s_tbl;
        const int n16 = SM_TBL_HALVES * 2 / 16;   // 8000 chunks
        for (int idx = t; idx < n16; idx += ATT_THREADS) dst[idx] = src[idx];
    }
    __syncthreads();

    const float4* s_q4 = (const float4*)s_q;

    // ---- QK^T + RPE (single pass over k) ----
    const float scale = 0.17677669529663687f;     // 1/sqrt(32)
    #pragma unroll
    for (int m = 0; m < KPT; m++) {
        int k = t + m * ATT_THREADS;
        const float* kv = g_kproj + (b * NK + k) * HD;
        float kvv[HD];
        #pragma unroll
        for (int d = 0; d < HD; d += 4) {
            float4 f = *(const float4*)(kv + d);
            kvv[d] = f.x; kvv[d+1] = f.y; kvv[d+2] = f.z; kvv[d+3] = f.w;
        }
        const float* xv = xyz + (b * NK + k) * 3;
        float kx = xv[0], ky = xv[1], kz = xv[2];

        float acc[NH];
        #pragma unroll
        for (int h = 0; h < NH; h++) {
            float a = 0.f;
            #pragma unroll
            for (int d4 = 0; d4 < HD / 4; d4++) {
                float4 q = s_q4[h * (HD / 4) + d4];
                a += q.x * kvv[d4 * 4 + 0];
                a += q.y * kvv[d4 * 4 + 1];
                a += q.z * kvv[d4 * 4 + 2];
                a += q.w * kvv[d4 * 4 + 3];
            }
            acc[h] = a * scale;
        }

        // RPE: all 8 tables from smem (fp16), accumulate into acc[]
        #pragma unroll
        for (int i = 0; i < NPTS; i++) {
            float gx = xform(s_rp[i*3+0] - kx);
            float gy = xform(s_rp[i*3+1] - ky);
            float gz = xform(s_rp[i*3+2] - kz);
            float fx = (gx + 1.f) * 4.5f, fy = (gy + 1.f) * 4.5f, fz = (gz + 1.f) * 4.5f;
            float x0f = floorf(fx), y0f = floorf(fy), z0f = floorf(fz);
            float wx1 = fx - x0f, wy1 = fy - y0f, wz1 = fz - z0f;
            int x0 = (int)x0f, y0 = (int)y0f, z0 = (int)z0f;
            const __half* base = s_tbl + i * NCELL * NH;
            #pragma unroll
            for (int c = 0; c < 8; c++) {
                int dz = c >> 2, dy = (c >> 1) & 1, dx = c & 1;
                int iz = z0 + dz, iy = y0 + dy, ix = x0 + dx;
                if ((unsigned)iz < 10u && (unsigned)iy < 10u && (unsigned)ix < 10u) {
                    float w = (dz ? wz1 : 1.f - wz1) * (dy ? wy1 : 1.f - wy1) * (dx ? wx1 : 1.f - wx1);
                    const __half2* tb = (const __half2*)(base + (iz * 100 + iy * 10 + ix) * NH);
                    // one 16B LDS: 4x half2
                    uint4 raw = *(const uint4*)tb;
                    __half2 p0 = *(const __half2*)&raw.x;
                    __half2 p1 = *(const __half2*)&raw.y;
                    __half2 p2 = *(const __half2*)&raw.z;
                    __half2 p3 = *(const __half2*)&raw.w;
                    float2 f0 = __half22float2(p0);
                    float2 f1 = __half22float2(p1);
                    float2 f2 = __half22float2(p2);
                    float2 f3 = __half22float2(p3);
                    acc[0] += w * f0.x; acc[1] += w * f0.y;
                    acc[2] += w * f1.x; acc[3] += w * f1.y;
                    acc[4] += w * f2.x; acc[5] += w * f2.y;
                    acc[6] += w * f3.x; acc[7] += w * f3.y;
                }
            }
        }
        #pragma unroll
        for (int h = 0; h < NH; h++) s_scores[h * NK + k] = acc[h];
    }
    __syncthreads();

    // ---- softmax (per head over NK) ----
    int lane = t & 31, wid = t >> 5;  // 16 warps
    #pragma unroll
    for (int h = 0; h < NH; h++) {
        float v = -1e30f;
        #pragma unroll
        for (int m = 0; m < KPT; m++) v = fmaxf(v, s_scores[h * NK + t + m * ATT_THREADS]);
        #pragma unroll
        for (int o = 16; o; o >>= 1) v = fmaxf(v, __shfl_xor_sync(0xffffffffu, v, o));
        if (lane == 0) s_red[h * 16 + wid] = v;
    }
    __syncthreads();
    if (t < NH) {
        float v = s_red[t * 16];
        for (int w2 = 1; w2 < 16; w2++) v = fmaxf(v, s_red[t * 16 + w2]);
        s_red[128 + t] = v;
    }
    __syncthreads();
    #pragma unroll
    for (int h = 0; h < NH; h++) {
        float mh = s_red[128 + h];
        float v = 0.f;
        #pragma unroll
        for (int m = 0; m < KPT; m++) {
            int k = t + m * ATT_THREADS;
            float e = expf(s_scores[h * NK + k] - mh);
            s_scores[h * NK + k] = e;
            v += e;
        }
        #pragma unroll
        for (int o = 16; o; o >>= 1) v += __shfl_xor_sync(0xffffffffu, v, o);
        if (lane == 0) s_red[h * 16 + wid] = v;
    }
    __syncthreads();
    if (t < NH) {
        float v = 0.f;
        for (int w2 = 0; w2 < 16; w2++) v += s_red[t * 16 + w2];
        s_red[136 + t] = 1.0f / v;
    }
    __syncthreads();
    #pragma unroll
    for (int h = 0; h < NH; h++) {
        float r = s_red[136 + h];
        #pragma unroll
        for (int m = 0; m < KPT; m++) {
            int k = t + m * ATT_THREADS;
            float p = s_scores[h * NK + k] * r;
            s_scores[h * NK + k] = p;
            out_attn[((size_t)(b * NH + h) * NQ + nq) * NK + k] = p;
        }
    }
    __syncthreads();

    // ---- AV: 512 threads = 2 k-halves x (8 heads x 32 dims) ----
    int half = t >> 8;
    int idx  = t & 255;
    int h = idx >> 5, d = idx & 31;
    float acc = 0.f;
    const float* vbase = g_vproj + b * NK * HD;
    int k0 = half * (NK / 2);
    int k1 = k0 + (NK / 2);
    for (; k0 < k1; k0 += 4) {
        float4 p = *(const float4*)&s_scores[h * NK + k0];
        acc += p.x * vbase[(k0 + 0) * HD + d];
        acc += p.y * vbase[(k0 + 1) * HD + d];
        acc += p.z * vbase[(k0 + 2) * HD + d];
        acc += p.w * vbase[(k0 + 3) * HD + d];
    }
    if (half) s_red[144 + idx] = acc;
    __syncthreads();
    if (!half) g_xmid[bq * DIM + idx] = acc + s_red[144 + idx];
}

// -------------------- output projection (+ transpose to (nQ,B,DIM)) --------------------
__global__ void k_proj(const float* __restrict__ w, const float* __restrict__ bias,
                       float* __restrict__ out_x) {
    __shared__ float row[DIM];
    int rid = blockIdx.x;               // b*NQ + nq
    int b = rid >> 8, nq = rid & 255;
    int t = threadIdx.x;
    row[t] = g_xmid[rid * DIM + t];
    __syncthreads();
    float acc = bias[t];
    #pragma unroll 4
    for (int c = 0; c < DIM; c++) acc += row[c] * w[c * DIM + t];
    out_x[(nq * BB + b) * DIM + t] = acc;
}

// -------------------- launch --------------------
extern "C" void kernel_launch(void* const* d_in, const int* in_sizes, int n_in,
                              void* d_out, int out_size) {
    const float* query = (const float*)d_in[0];
    const float* key   = (const float*)d_in[1];
    const float* refpt = (const float*)d_in[2];
    // d_in[3] reference_angle: unused by the reference computation
    const float* xyz   = (const float*)d_in[4];
    const float* q_w   = (const float*)d_in[5];
    const float* q_b   = (const float*)d_in[6];
    const float* k_w   = (const float*)d_in[7];
    const float* k_b   = (const float*)d_in[8];
    const float* v_w   = (const float*)d_in[9];
    const float* v_b   = (const float*)d_in[10];
    const float* p_w   = (const float*)d_in[11];
    const float* p_b   = (const float*)d_in[12];
    const float* w1    = (const float*)d_in[13];
    const float* b1    = (const float*)d_in[14];
    const float* w2    = (const float*)d_in[15];

    float* out_x    = (float*)d_out;                       // (nQ, B, DIM)
    float* out_attn = (float*)d_out + BB * NQ * DIM;       // (B, NH, nQ, nK)

    const int smem_bytes = SM_TOTAL_F * (int)sizeof(float);
    cudaFuncSetAttribute(k_attn, cudaFuncAttributeMaxDynamicSharedMemorySize, smem_bytes);

    k_tables<<<(NPTS * NCELL + 255) / 256, 256>>>(w1, b1, w2);
    k_qproj <<<BB * NQ, 256>>>(query, q_w, q_b);
    k_kvproj<<<BB * NK, 64>>>(key, k_w, k_b, v_w, v_b);
    k_attn  <<<BB * NQ, ATT_THREADS, smem_bytes>>>(refpt, xyz, out_attn);
    k_proj  <<<BB * NQ, 256>>>(p_w, p_b, out_x);
}